// round 1
// baseline (speedup 1.0000x reference)
#include <cuda_runtime.h>
#include <cstdint>

// ProcessorNet: x[B,128]; 64 sequential steps:
//   reg = relu(x@wd.T + bd) * inst_t ; x += reg@wu.T + bu
// Reduced form (exact up to fp reassociation):
//   z_0 = x@wd.T + bd                          [B,16]
//   z_{t+1} = z_t + (relu(z_t)*inst_t)@A + c   A = wu.T@wd.T [16,16], c = bu@wd.T
//   out = x + (sum_t relu(z_t)*inst_t)@wu.T + 64*bu

#define HDIM 128
#define WDIM 16
#define LSTEPS 64

struct Consts {
    float2 A2[17][16];      // A2[j][i] splat; row 16 holds c (paired with r=1)
    float  prog[LSTEPS][16];
    float2 wd2[128][16];    // [h][i] = splat(wd[i*128+h])
    float2 wu2[128][16];    // [h][j] = splat(wu[h*16+j])
    float2 bd2[16];
    float2 bu2[128];        // splat(64*bu[h])
};

__device__ Consts g_c;

__global__ void setup_kernel(const float* __restrict__ prog,
                             const float* __restrict__ wd,
                             const float* __restrict__ bd,
                             const float* __restrict__ wu,
                             const float* __restrict__ bu) {
    int tid = threadIdx.x;  // 256 threads
    // A[j][i] = sum_h wu[h][j] * wd[i][h]
    {
        int j = tid >> 4, i = tid & 15;
        float s = 0.f;
        #pragma unroll 8
        for (int h = 0; h < HDIM; ++h) s += wu[h * WDIM + j] * wd[i * HDIM + h];
        g_c.A2[j][i] = make_float2(s, s);
    }
    if (tid < 16) {
        int i = tid;
        float s = 0.f;
        #pragma unroll 8
        for (int h = 0; h < HDIM; ++h) s += bu[h] * wd[i * HDIM + h];
        g_c.A2[16][i] = make_float2(s, s);   // c row
        float b = bd[i];
        g_c.bd2[i] = make_float2(b, b);
    }
    for (int idx = tid; idx < LSTEPS * 16; idx += 256)
        g_c.prog[idx >> 4][idx & 15] = prog[idx];
    for (int idx = tid; idx < 128 * 16; idx += 256) {
        int h = idx >> 4, i = idx & 15;
        float v = wd[i * HDIM + h];
        g_c.wd2[h][i] = make_float2(v, v);
        float u = wu[h * WDIM + i];
        g_c.wu2[h][i] = make_float2(u, u);
    }
    for (int idx = tid; idx < 128; idx += 256) {
        float v = 64.f * bu[idx];
        g_c.bu2[idx] = make_float2(v, v);
    }
}

// ---- packed f32x2 helpers (Blackwell fma.rn.f32x2 — 2x fp32 throughput) ----
typedef unsigned long long u64;

__device__ __forceinline__ u64 pk(float x, float y) {
    u64 r;
    asm("mov.b64 %0, {%1, %2};" : "=l"(r) : "f"(x), "f"(y));
    return r;
}
__device__ __forceinline__ void upk(u64 v, float& x, float& y) {
    asm("mov.b64 {%0, %1}, %2;" : "=f"(x), "=f"(y) : "l"(v));
}
__device__ __forceinline__ u64 f2u(float2 v) { return pk(v.x, v.y); }
__device__ __forceinline__ u64 fma2(u64 a, u64 b, u64 c) {
    u64 d;
    asm("fma.rn.f32x2 %0, %1, %2, %3;" : "=l"(d) : "l"(a), "l"(b), "l"(c));
    return d;
}
__device__ __forceinline__ u64 add2(u64 a, u64 b) {
    u64 d;
    asm("add.rn.f32x2 %0, %1, %2;" : "=l"(d) : "l"(a), "l"(b));
    return d;
}

__global__ __launch_bounds__(256)
void proc_kernel(const float* __restrict__ x, float* __restrict__ out) {
    __shared__ Consts s;
    {   // cooperative copy of constants into shared
        const float4* src = (const float4*)&g_c;
        float4* dst = (float4*)&s;
        const int n = (int)(sizeof(Consts) / 16);
        for (int i = threadIdx.x; i < n; i += 256) dst[i] = src[i];
    }
    __syncthreads();

    size_t pair = (size_t)blockIdx.x * 256 + threadIdx.x;  // 2 rows per thread
    const float* x0 = x + pair * 2 * HDIM;
    const float* x1 = x0 + HDIM;
    float* o0 = out + pair * 2 * HDIM;
    float* o1 = o0 + HDIM;

    u64 z[16], R[16];
    #pragma unroll
    for (int i = 0; i < 16; i++) { z[i] = f2u(s.bd2[i]); R[i] = 0ull; }

    // ---- phase A: z = x @ wd.T + bd ----
    #pragma unroll 2
    for (int h = 0; h < HDIM; h += 4) {
        float4 a0 = *(const float4*)(x0 + h);
        float4 a1 = *(const float4*)(x1 + h);
        float av0[4] = {a0.x, a0.y, a0.z, a0.w};
        float av1[4] = {a1.x, a1.y, a1.z, a1.w};
        #pragma unroll
        for (int k = 0; k < 4; k++) {
            u64 xv = pk(av0[k], av1[k]);
            const ulonglong2* wrow = (const ulonglong2*)&s.wd2[h + k][0];
            #pragma unroll
            for (int i = 0; i < 16; i += 2) {
                ulonglong2 w = wrow[i >> 1];
                z[i]     = fma2(xv, w.x, z[i]);
                z[i + 1] = fma2(xv, w.y, z[i + 1]);
            }
        }
    }

    // ---- phase B: 64-step recurrence in 16-dim space ----
    const u64 one2 = pk(1.f, 1.f);
    #pragma unroll 1
    for (int t = 0; t < LSTEPS; t++) {
        u64 r[16];
        #pragma unroll
        for (int j = 0; j < 16; j++) {
            float zx, zy;
            upk(z[j], zx, zy);
            float p = s.prog[t][j];
            float rx = fmaxf(zx, 0.f) * p;
            float ry = fmaxf(zy, 0.f) * p;
            r[j] = pk(rx, ry);
            R[j] = add2(R[j], r[j]);
        }
        #pragma unroll
        for (int j = 0; j < 17; j++) {
            u64 rj = (j < 16) ? r[j] : one2;   // row 16 of A is c, paired with 1.0
            const ulonglong2* arow = (const ulonglong2*)&s.A2[j][0];
            #pragma unroll
            for (int i = 0; i < 16; i += 2) {
                ulonglong2 a = arow[i >> 1];
                z[i]     = fma2(rj, a.x, z[i]);
                z[i + 1] = fma2(rj, a.y, z[i + 1]);
            }
        }
    }

    // ---- phase C: out = x + R @ wu.T + 64*bu ----
    #pragma unroll 2
    for (int h = 0; h < HDIM; h += 4) {
        float4 a0 = *(const float4*)(x0 + h);
        float4 a1 = *(const float4*)(x1 + h);
        float av0[4] = {a0.x, a0.y, a0.z, a0.w};
        float av1[4] = {a1.x, a1.y, a1.z, a1.w};
        float b0[4], b1[4];
        #pragma unroll
        for (int k = 0; k < 4; k++) {
            u64 acc = add2(pk(av0[k], av1[k]), f2u(s.bu2[h + k]));
            const ulonglong2* urow = (const ulonglong2*)&s.wu2[h + k][0];
            #pragma unroll
            for (int j = 0; j < 16; j += 2) {
                ulonglong2 u = urow[j >> 1];
                acc = fma2(R[j], u.x, acc);
                acc = fma2(R[j + 1], u.y, acc);
            }
            float ox, oy;
            upk(acc, ox, oy);
            b0[k] = ox;
            b1[k] = oy;
        }
        *(float4*)(o0 + h) = make_float4(b0[0], b0[1], b0[2], b0[3]);
        *(float4*)(o1 + h) = make_float4(b1[0], b1[1], b1[2], b1[3]);
    }
}

extern "C" void kernel_launch(void* const* d_in, const int* in_sizes, int n_in,
                              void* d_out, int out_size) {
    const float* x    = (const float*)d_in[0];
    const float* prog = (const float*)d_in[1];
    const float* wd   = (const float*)d_in[2];
    const float* bd   = (const float*)d_in[3];
    const float* wu   = (const float*)d_in[4];
    const float* bu   = (const float*)d_in[5];
    float* out = (float*)d_out;

    setup_kernel<<<1, 256>>>(prog, wd, bd, wu, bu);

    // B = 262144 rows, 2 rows/thread, 256 threads/block -> 512 blocks
    int pairs = (in_sizes[0] / HDIM) / 2;
    int blocks = (pairs + 255) / 256;
    proc_kernel<<<blocks, 256>>>(x, out);
}